// round 15
// baseline (speedup 1.0000x reference)
#include <cuda_runtime.h>
#include <cuda_fp16.h>
#include <math.h>
#include <cstdint>

#define B 8
#define C 64
#define H 256
#define W 256
#define HW 65536
#define P 16
#define OC 64
#define NBINS 256
#define OUTC 112   // OC + (C-P)

// Device scratch
__device__ float g_act[B * C];
__device__ int   g_unsel[B * (C - P)];
__device__ uint4 g_pack[B * HW * 2];   // [b][px][16ch] fp16, 32B per px

__device__ __forceinline__ uint32_t smem_u32(const void* p) {
    uint32_t a;
    asm("{ .reg .u64 t; cvta.to.shared.u64 t, %1; cvt.u32.u64 %0, t; }"
        : "=r"(a) : "l"(p));
    return a;
}
__device__ __forceinline__ void cp_async16(uint32_t saddr, const void* g) {
    asm volatile("cp.async.cg.shared.global [%0], [%1], 16;"
                 :: "r"(saddr), "l"(g) : "memory");
}

// ===========================================================================
// Kernel 1: fused per-(b,c) min/max + 256-bin histogram + entropy.
// ===========================================================================
__global__ void __launch_bounds__(512)
k_stats(const float* __restrict__ x) {
    __shared__ float smn[512], smx[512];
    __shared__ int   sh[16][NBINS];
    __shared__ float sred[512];
    __shared__ float s_mn, s_den;

    int bc  = blockIdx.x;
    int tid = threadIdx.x;
    int wid = tid >> 5;
    const float4* p = (const float4*)(x + (size_t)bc * HW);

    float mn = 3.402823466e+38f, mx = -3.402823466e+38f;
#pragma unroll 4
    for (int i = tid; i < HW / 4; i += 512) {
        float4 v = p[i];
        mn = fminf(mn, fminf(fminf(v.x, v.y), fminf(v.z, v.w)));
        mx = fmaxf(mx, fmaxf(fmaxf(v.x, v.y), fmaxf(v.z, v.w)));
    }
    smn[tid] = mn; smx[tid] = mx;
    for (int w = 0; w < 16; w++)
        if (tid < NBINS) sh[w][tid] = 0;
    __syncthreads();
    for (int s = 256; s > 0; s >>= 1) {
        if (tid < s) {
            smn[tid] = fminf(smn[tid], smn[tid + s]);
            smx[tid] = fmaxf(smx[tid], smx[tid + s]);
        }
        __syncthreads();
    }
    if (tid == 0) { s_mn = smn[0]; s_den = smx[0] - smn[0] + 1e-8f; }
    __syncthreads();

    float bmn  = s_mn, bden = s_den;
    float binv = __frcp_rn(bden);
    int* myh = sh[wid];
#pragma unroll 2
    for (int i = tid; i < HW / 4; i += 512) {
        float4 v = p[i];
        float vs[4] = {v.x, v.y, v.z, v.w};
#pragma unroll
        for (int k = 0; k < 4; k++) {
            float d  = vs[k] - bmn;
            float q0 = d * binv;                 // Markstein: matches div.rn
            float r  = fmaf(-bden, q0, d);
            float xn = fmaf(r, binv, q0);
            int bn = (int)(xn * 256.0f);
            bn = bn < 0 ? 0 : (bn > 255 ? 255 : bn);
            atomicAdd(&myh[bn], 1);
        }
    }
    __syncthreads();

    float hv = 0.f;
    if (tid < NBINS) {
        int cnt = 0;
#pragma unroll
        for (int w = 0; w < 16; w++) cnt += sh[w][tid];
        hv = (float)cnt + 1e-8f;
    }
    sred[tid] = hv;
    __syncthreads();
    for (int s = 256; s > 0; s >>= 1) {
        if (tid < s) sred[tid] += sred[tid + s];
        __syncthreads();
    }
    float total = sred[0];
    __syncthreads();

    float term = 0.f;
    if (tid < NBINS) {
        float prob = __fdiv_rn(hv, total);
        term = prob * logf(prob + 1e-8f);
    }
    sred[tid] = term;
    __syncthreads();
    for (int s = 256; s > 0; s >>= 1) {
        if (tid < s) sred[tid] += sred[tid + s];
        __syncthreads();
    }
    if (tid == 0) g_act[bc] = -sred[0];
}

// ===========================================================================
// Kernel 2: topk (recomputed per block) + gather+pack -> g_pack.
// Each block re-derives the stable top-16 for its batch from g_act;
// one block per batch publishes g_unsel for the conv kernel's copy.
// ===========================================================================
__global__ void __launch_bounds__(256)
k_gather(const float* __restrict__ x) {
    __shared__ float sa[C];
    __shared__ int   sTop[P];
    int blk = blockIdx.x;          // B * 128 blocks, 512 px each
    int b   = blk >> 7;
    int px0 = (blk & 127) << 9;

    if (threadIdx.x < C) sa[threadIdx.x] = g_act[b * C + threadIdx.x];
    __syncthreads();
    if (threadIdx.x == 0) {
        bool used[C];
        for (int c = 0; c < C; c++) used[c] = false;
        for (int p = 0; p < P; p++) {
            float best = -3.402823466e+38f;
            int bi = -1;
            for (int c = 0; c < C; c++)
                if (!used[c] && sa[c] > best) { best = sa[c]; bi = c; }
            used[bi] = true;
            sTop[p] = bi;
        }
        if ((blk & 127) == 0) {
            int k = 0;
            for (int c = 0; c < C; c++)
                if (!used[c]) g_unsel[b * (C - P) + (k++)] = c;
        }
    }
    __syncthreads();

    int ch[16];
#pragma unroll
    for (int c = 0; c < 16; c++) ch[c] = sTop[c];
    const float* xb = x + ((size_t)b * C) * HW;
#pragma unroll
    for (int u = 0; u < 2; u++) {
        int px = px0 + u * 256 + threadIdx.x;
        uint32_t q[8];
#pragma unroll
        for (int c2 = 0; c2 < 8; c2++) {
            float f0 = xb[(size_t)ch[2 * c2]     * HW + px];
            float f1 = xb[(size_t)ch[2 * c2 + 1] * HW + px];
            __half2 hp = __floats2half2_rn(f0, f1);
            q[c2] = *reinterpret_cast<uint32_t*>(&hp);
        }
        uint4* dst = g_pack + ((size_t)b * HW + px) * 2;
        dst[0] = make_uint4(q[0], q[1], q[2], q[3]);
        dst[1] = make_uint4(q[4], q[5], q[6], q[7]);
    }
}

// ===========================================================================
// Kernel 3: persistent fp16 mma conv, vertical ring walk, copy via cp.async.
// 16 strips x 27 CTAs; per tile: wait -> consume copy(t) from smem ->
// issue {ring row h+2, copy chunk t+1} cp.async group -> mainloop -> stores.
// Copy staging overlaps mainloop; no exposed DRAM read latency per tile.
// ===========================================================================
#define APITCH 12
#define AROW   132
#define RING_WORDS (4 * AROW * APITCH)       // 6336
#define SWF_UINT4  (9 * 4 * 32)              // 1152 fragments
#define CP_UINT4   (6 * 256)                 // 1536 (24576B)
#define CONV_SMEM  (RING_WORDS * 4 + SWF_UINT4 * 16 + CP_UINT4 * 16)  // 68352
#define NSTRIP 16
#define CPS    27
#define NCTA   (NSTRIP * CPS)                // 432
#define COPY_F4_PER_TILE 1536                // 6291456 / 4096

__global__ void __launch_bounds__(256, 3)
k_conv_mma(const float* __restrict__ x, const float* __restrict__ wgt,
           const float* __restrict__ bias, float* __restrict__ out) {
    extern __shared__ uint32_t smem_w[];
    uint32_t* ring = smem_w;
    uint4*    sWf  = (uint4*)(smem_w + RING_WORDS);
    uint4*    sCp  = sWf + SWF_UINT4;
    __shared__ float sB[OC];

    int tid  = threadIdx.x;
    int wid  = tid >> 5;
    int lane = tid & 31;
    uint32_t ringA = smem_u32(ring);
    uint32_t sCpA  = smem_u32(sCp);

    // one-time: pre-packed weight fragments + bias
    for (int i = tid; i < SWF_UINT4; i += 256) {
        int tap = i >> 7;
        int mi  = (i >> 5) & 3;
        int ln  = i & 31;
        int gp_ = ln >> 2;
        int kc_ = ln & 3;
        int oc0 = mi * 16 + gp_;
        auto pk = [&](int oc, int k2) -> uint32_t {
            float f0 = wgt[oc * (P * 9) + (2 * k2)     * 9 + tap];
            float f1 = wgt[oc * (P * 9) + (2 * k2 + 1) * 9 + tap];
            __half2 hp = __floats2half2_rn(f0, f1);
            return *reinterpret_cast<uint32_t*>(&hp);
        };
        sWf[i] = make_uint4(pk(oc0, kc_), pk(oc0 + 8, kc_),
                            pk(oc0, kc_ + 4), pk(oc0 + 8, kc_ + 4));
    }
    if (tid < OC) sB[tid] = bias[tid];

    int strip = blockIdx.x / CPS;
    int k     = blockIdx.x - strip * CPS;
    int b     = strip >> 1;
    int w0    = (strip & 1) * 128;
    int hs    = k * 9 + (k < 13 ? k : 13);
    int cnt   = 9 + (k < 13 ? 1 : 0);
    int he    = hs + cnt;

    int gp = lane >> 2;
    int kc = lane & 3;
    int pxchunk = wid;

    // stage one absolute input row r into ring buffer (r&3); no commit
    auto stage_row = [&](int r) {
        int rb = (r + 4) & 3;
        uint32_t dstb = ringA + (uint32_t)(rb * AROW * APITCH) * 4u;
        if ((unsigned)r < (unsigned)H) {
            const uint4* srow = g_pack + ((size_t)b * HW + r * W) * 2;
            for (int pp = tid; pp < 130; pp += 256) {
                int gw = w0 - 1 + pp;
                uint32_t dst = dstb + (uint32_t)(pp * APITCH) * 4u;
                if ((unsigned)gw < (unsigned)W) {
                    const uint4* src = srow + gw * 2;
                    cp_async16(dst,       src);
                    cp_async16(dst + 16u, src + 1);
                } else {
                    uint4 z = make_uint4(0u, 0u, 0u, 0u);
                    *(uint4*)((char*)ring + (dst - ringA))      = z;
                    *(uint4*)((char*)ring + (dst - ringA) + 16) = z;
                }
            }
        } else {
            uint4 z = make_uint4(0u, 0u, 0u, 0u);
            for (int pp = tid; pp < 130; pp += 256) {
                uint32_t off = (uint32_t)((rb * AROW + pp) * APITCH) * 4u;
                *(uint4*)((char*)ring + off)      = z;
                *(uint4*)((char*)ring + off + 16) = z;
            }
        }
    };

    // stage copy chunk for tile into sCp (tid-owned slots); no commit
    auto stage_copy = [&](int tile) {
        size_t base = (size_t)tile * COPY_F4_PER_TILE;
#pragma unroll
        for (int u = 0; u < 6; u++) {
            size_t tt = base + u * 256 + tid;
            int ch_slot = (int)(tt >> 14);
            int off     = (int)(tt & 16383);
            int cb = ch_slot / (C - P);
            int j  = ch_slot - cb * (C - P);
            int cc = __ldg(&g_unsel[cb * (C - P) + j]);
            const float4* src =
                ((const float4*)(x + ((size_t)(cb * C + cc)) * HW)) + off;
            cp_async16(sCpA + (uint32_t)(u * 256 + tid) * 16u, src);
        }
    };

    // prologue: rows hs-1..hs+1 + copy(first tile), one group
    stage_row(hs - 1);
    stage_row(hs);
    stage_row(hs + 1);
    stage_copy(strip * 256 + hs);
    asm volatile("cp.async.commit_group;" ::: "memory");
    __syncthreads();   // sWf/sB + zero-fills visible

    for (int h = hs; h < he; h++) {
        asm volatile("cp.async.wait_group 0;" ::: "memory");

        // consume copy chunk for tile t (own slots; no barrier needed)
        {
            size_t base = (size_t)(strip * 256 + h) * COPY_F4_PER_TILE;
#pragma unroll
            for (int u = 0; u < 6; u++) {
                size_t tt = base + u * 256 + tid;
                int ch_slot = (int)(tt >> 14);
                int off     = (int)(tt & 16383);
                int cb = ch_slot / (C - P);
                int j  = ch_slot - cb * (C - P);
                uint4 v = sCp[u * 256 + tid];
                float4* dst =
                    ((float4*)(out + (((size_t)cb * OUTC) + OC + j) * HW)) + off;
                *dst = *(float4*)&v;
            }
        }

        // issue next group: ring row h+2 + copy chunk t+1
        bool pf = (h + 1 < he);
        if (pf) {
            stage_row(h + 2);
            stage_copy(strip * 256 + h + 1);
            asm volatile("cp.async.commit_group;" ::: "memory");
        }
        __syncthreads();   // ring rows for tile h visible to all warps

        // mainloop
        float acc[4][2][4];
#pragma unroll
        for (int mi = 0; mi < 4; mi++)
#pragma unroll
            for (int ni = 0; ni < 2; ni++)
#pragma unroll
                for (int r = 0; r < 4; r++) acc[mi][ni][r] = 0.f;

#pragma unroll
        for (int tap = 0; tap < 9; tap++) {
            int kh = tap / 3, kw = tap - kh * 3;
            int rb = (h - 1 + kh + 4) & 3;
            uint32_t bf[2][2];
#pragma unroll
            for (int ni = 0; ni < 2; ni++) {
                int slot = rb * AROW + pxchunk * 16 + ni * 8 + gp + kw;
                bf[ni][0] = ring[slot * APITCH + kc];
                bf[ni][1] = ring[slot * APITCH + kc + 4];
            }
#pragma unroll
            for (int mi = 0; mi < 4; mi++) {
                uint4 av = sWf[(tap * 4 + mi) * 32 + lane];   // LDS.128
#pragma unroll
                for (int ni = 0; ni < 2; ni++) {
                    asm volatile(
                        "mma.sync.aligned.m16n8k16.row.col.f32.f16.f16.f32 "
                        "{%0,%1,%2,%3}, {%4,%5,%6,%7}, {%8,%9}, {%0,%1,%2,%3};"
                        : "+f"(acc[mi][ni][0]), "+f"(acc[mi][ni][1]),
                          "+f"(acc[mi][ni][2]), "+f"(acc[mi][ni][3])
                        : "r"(av.x), "r"(av.y), "r"(av.z), "r"(av.w),
                          "r"(bf[ni][0]), "r"(bf[ni][1]));
                }
            }
        }

        // epilogue: STG.64 (adjacent px pairs)
        size_t obase = ((size_t)b * OUTC) * HW + (size_t)h * W + w0
                     + pxchunk * 16 + 2 * kc;
#pragma unroll
        for (int mi = 0; mi < 4; mi++) {
            int oc0 = mi * 16 + gp;
            float bb0 = sB[oc0], bb8 = sB[oc0 + 8];
            float* o0 = out + obase + (size_t)oc0 * HW;
            float* o8 = o0 + (size_t)8 * HW;
#pragma unroll
            for (int ni = 0; ni < 2; ni++) {
                float2 v0 = make_float2(acc[mi][ni][0] + bb0, acc[mi][ni][1] + bb0);
                float2 v1 = make_float2(acc[mi][ni][2] + bb8, acc[mi][ni][3] + bb8);
                *(float2*)(o0 + ni * 8) = v0;
                *(float2*)(o8 + ni * 8) = v1;
            }
        }
        __syncthreads();   // ring reads done before next-row overwrite lands
    }
}

// ===========================================================================
extern "C" void kernel_launch(void* const* d_in, const int* in_sizes, int n_in,
                              void* d_out, int out_size) {
    const float* x    = (const float*)d_in[0];
    const float* wgt  = (const float*)d_in[1];
    const float* bias = (const float*)d_in[2];
    float* out = (float*)d_out;

    cudaFuncSetAttribute(k_conv_mma, cudaFuncAttributeMaxDynamicSharedMemorySize,
                         CONV_SMEM);

    k_stats<<<B * C, 512>>>(x);
    k_gather<<<B * 128, 256>>>(x);
    k_conv_mma<<<NCTA, 256, CONV_SMEM>>>(x, wgt, bias, out);
}